// round 1
// baseline (speedup 1.0000x reference)
#include <cuda_runtime.h>
#include <cuda_bf16.h>
#include <cstdint>

// Problem shape (fixed by reference)
#define PN 8
#define PH 32
#define PL 512
#define PS 512
#define MAXP 100
#define TPAD (MAXP + 1)   // 101: padded stride so bank = (5h+p)%32 (conflict-free-ish)

__global__ __launch_bounds__(256)
void gpe_kernel(const float* __restrict__ QK,
                const int* __restrict__ pos,
                const float* __restrict__ table,
                float* __restrict__ out) {
    __shared__ float t_sh[PH * TPAD];   // transposed table: t_sh[h*101 + p]
    __shared__ int   p_sh[PS];          // pos row for this (n, l)

    const int bid = blockIdx.x;         // n*PL + l
    const int n = bid >> 9;             // / 512
    const int l = bid & (PL - 1);
    const int tid = threadIdx.x;

    // Stage table (transposed), zeroing padding row 0
    #pragma unroll 4
    for (int i = tid; i < PH * MAXP; i += 256) {
        const int p = i / PH;
        const int h = i - p * PH;
        const float v = (p == 0) ? 0.0f : __ldg(&table[p * PH + h]);
        t_sh[h * TPAD + p] = v;
    }

    // Stage pos row (512 ints = 128 int4) — vectorized
    {
        const int4* pos4 = reinterpret_cast<const int4*>(
            pos + ((size_t)n * PL + l) * PS);
        int4* p_sh4 = reinterpret_cast<int4*>(p_sh);
        if (tid < PS / 4) {
            p_sh4[tid] = pos4[tid];
        }
    }
    __syncthreads();

    // Stream QK: 32 heads x 128 float4 per row = 4096 units, 256 threads -> 16 iters
    const size_t base = ((size_t)n * PH) * (size_t)(PL * PS) + (size_t)l * PS;
    const int4* p_sh4 = reinterpret_cast<const int4*>(p_sh);

    #pragma unroll 4
    for (int it = tid; it < PH * (PS / 4); it += 256) {
        const int h  = it >> 7;          // / 128
        const int s4 = it & 127;
        const size_t idx = base + (size_t)h * (PL * PS) + (size_t)(s4 << 2);

        float4 q = *reinterpret_cast<const float4*>(QK + idx);
        const int4 p4 = p_sh4[s4];
        const float* th = &t_sh[h * TPAD];
        q.x += th[p4.x];
        q.y += th[p4.y];
        q.z += th[p4.z];
        q.w += th[p4.w];
        *reinterpret_cast<float4*>(out + idx) = q;
    }
}

extern "C" void kernel_launch(void* const* d_in, const int* in_sizes, int n_in,
                              void* d_out, int out_size) {
    const float* QK    = (const float*)d_in[0];
    const int*   pos   = (const int*)d_in[1];
    const float* table = (const float*)d_in[2];
    float* out = (float*)d_out;

    const int blocks = PN * PL;   // 4096
    gpe_kernel<<<blocks, 256>>>(QK, pos, table, out);
}

// round 2
// speedup vs baseline: 1.1275x; 1.1275x over previous
#include <cuda_runtime.h>
#include <cuda_bf16.h>
#include <cstdint>

// Problem shape (fixed by reference)
#define PN 8
#define PH 32
#define PL 512
#define PS 512
#define PLS (PL * PS)
#define MAXP 100
#define TPAD (MAXP + 1)   // 101: pad so bank = (5h + p) % 32 across h

__global__ __launch_bounds__(256, 6)
void gpe_kernel(const float* __restrict__ QK,
                const int* __restrict__ pos,
                const float* __restrict__ table,
                float* __restrict__ out) {
    __shared__ float t_sh[PH * TPAD];   // transposed table: t_sh[h*101 + p]

    const int bid = blockIdx.x;         // n*PL + l
    const int n = bid >> 9;
    const int l = bid & (PL - 1);
    const int tid = threadIdx.x;

    // Stage table (transposed), zeroing padding row 0.
    // i consecutive -> h consecutive: coalesced 32-element reads per p.
    #pragma unroll 4
    for (int i = tid; i < PH * MAXP; i += 256) {
        const int p = i >> 5;
        const int h = i & 31;
        const float v = (p == 0) ? 0.0f : __ldg(&table[p * PH + h]);
        t_sh[h * TPAD + p] = v;
    }

    // Each thread owns one s4 (group of 4 s values) and 16 of the 32 heads.
    const int s4 = tid & 127;           // 0..127
    const int h0 = tid >> 7;            // 0 or 1

    // pos for this (n, l, s4) — read exactly once, coalesced int4
    const int4 p4 = __ldg(reinterpret_cast<const int4*>(
        pos + ((size_t)n * PL + l) * PS) + s4);

    __syncthreads();

    // Base element index for (n, h0, l, s4*4)
    size_t idx = ((size_t)n * PH + h0) * (size_t)PLS
               + (size_t)l * PS + ((size_t)s4 << 2);

    const float* th = &t_sh[h0 * TPAD];

    #pragma unroll
    for (int k = 0; k < 16; k++) {
        float4 q = __ldcs(reinterpret_cast<const float4*>(QK + idx));
        float4 b;
        b.x = th[p4.x];
        b.y = th[p4.y];
        b.z = th[p4.z];
        b.w = th[p4.w];
        q.x += b.x; q.y += b.y; q.z += b.z; q.w += b.w;
        __stcg(reinterpret_cast<float4*>(out + idx), q);
        idx += (size_t)2 * PLS;         // next h (h += 2)
        th  += 2 * TPAD;
    }
}

extern "C" void kernel_launch(void* const* d_in, const int* in_sizes, int n_in,
                              void* d_out, int out_size) {
    const float* QK    = (const float*)d_in[0];
    const int*   pos   = (const int*)d_in[1];
    const float* table = (const float*)d_in[2];
    float* out = (float*)d_out;

    const int blocks = PN * PL;   // 4096
    gpe_kernel<<<blocks, 256>>>(QK, pos, table, out);
}

// round 3
// speedup vs baseline: 1.1327x; 1.0046x over previous
#include <cuda_runtime.h>
#include <cuda_bf16.h>
#include <cstdint>

// Problem shape (fixed by reference)
#define PN 8
#define PH 32
#define PL 512
#define PS 512
#define PLS (PL * PS)
#define MAXP 100
#define TPAD (MAXP + 1)   // 101: bank = (5h + p) % 32 across h
#define LPB 2             // l values per block

__global__ __launch_bounds__(256, 6)
void gpe_kernel(const float* __restrict__ QK,
                const int* __restrict__ pos,
                const float* __restrict__ table,
                float* __restrict__ out) {
    __shared__ float t_sh[PH * TPAD];   // transposed table: t_sh[h*101 + p]

    const int bid = blockIdx.x;           // n * 256 + l0/2
    const int n  = bid >> 8;              // / (PL/LPB)
    const int l0 = (bid & 255) << 1;      // first of 2 l values
    const int tid = threadIdx.x;

    // Stage table (transposed), zeroing padding row 0.
    #pragma unroll 4
    for (int i = tid; i < PH * MAXP; i += 256) {
        const int p = i >> 5;
        const int h = i & 31;
        const float v = (p == 0) ? 0.0f : __ldg(&table[p * PH + h]);
        t_sh[h * TPAD + p] = v;
    }

    // Each thread owns one s4 (group of 4 s) and 16 of the 32 heads.
    const int s4 = tid & 127;
    const int h0 = tid >> 7;              // 0 or 1

    // pos for both l values — issued before the barrier to hide latency
    int4 p4[LPB];
    #pragma unroll
    for (int li = 0; li < LPB; li++) {
        p4[li] = __ldg(reinterpret_cast<const int4*>(
            pos + ((size_t)n * PL + (l0 + li)) * PS) + s4);
    }

    __syncthreads();

    #pragma unroll
    for (int li = 0; li < LPB; li++) {
        const size_t base = ((size_t)n * PH + h0) * (size_t)PLS
                          + (size_t)(l0 + li) * PS + ((size_t)s4 << 2);
        const int4 pp = p4[li];

        #pragma unroll
        for (int kb = 0; kb < 4; kb++) {
            // 4 independent loads (h = h0 + 2*(4*kb + j)), batched for MLP
            const size_t idx0 = base + (size_t)(kb * 8) * PLS;
            float4 q0 = __ldcs(reinterpret_cast<const float4*>(QK + idx0));
            float4 q1 = __ldcs(reinterpret_cast<const float4*>(QK + idx0 + (size_t)2 * PLS));
            float4 q2 = __ldcs(reinterpret_cast<const float4*>(QK + idx0 + (size_t)4 * PLS));
            float4 q3 = __ldcs(reinterpret_cast<const float4*>(QK + idx0 + (size_t)6 * PLS));

            const int hbase = h0 + 8 * kb;         // h for j=0
            const float* th0 = &t_sh[hbase * TPAD];
            const float* th1 = th0 + 2 * TPAD;
            const float* th2 = th0 + 4 * TPAD;
            const float* th3 = th0 + 6 * TPAD;

            q0.x += th0[pp.x]; q0.y += th0[pp.y]; q0.z += th0[pp.z]; q0.w += th0[pp.w];
            q1.x += th1[pp.x]; q1.y += th1[pp.y]; q1.z += th1[pp.z]; q1.w += th1[pp.w];
            q2.x += th2[pp.x]; q2.y += th2[pp.y]; q2.z += th2[pp.z]; q2.w += th2[pp.w];
            q3.x += th3[pp.x]; q3.y += th3[pp.y]; q3.z += th3[pp.z]; q3.w += th3[pp.w];

            __stcg(reinterpret_cast<float4*>(out + idx0), q0);
            __stcg(reinterpret_cast<float4*>(out + idx0 + (size_t)2 * PLS), q1);
            __stcg(reinterpret_cast<float4*>(out + idx0 + (size_t)4 * PLS), q2);
            __stcg(reinterpret_cast<float4*>(out + idx0 + (size_t)6 * PLS), q3);
        }
    }
}

extern "C" void kernel_launch(void* const* d_in, const int* in_sizes, int n_in,
                              void* d_out, int out_size) {
    const float* QK    = (const float*)d_in[0];
    const int*   pos   = (const int*)d_in[1];
    const float* table = (const float*)d_in[2];
    float* out = (float*)d_out;

    const int blocks = PN * PL / LPB;   // 2048
    gpe_kernel<<<blocks, 256>>>(QK, pos, table, out);
}